// round 17
// baseline (speedup 1.0000x reference)
#include <cuda_runtime.h>
#include <cuda_fp16.h>
#include <cstdint>
#include <cstddef>

#define DIM 1024
#define NH 16
#define HD 64
#define NB 8
#define LQ 512
#define LKK 1024
#define MQ (NB*LQ)      // 4096
#define MK (NB*LKK)     // 8192
#define EPSV 1e-5f
#define QSCALE 0.125f
#define WUP 32.0f
#define WINV (1.0f/32.0f)

// ------------------------- scratch -------------------------
__device__ float g_att[(size_t)MQ * DIM];

__device__ __half g_tAhi[(size_t)MQ * DIM];
__device__ __half g_tVhi[(size_t)MK * DIM];
__device__ __half g_tWhi[(size_t)3*DIM*DIM];
__device__ __half g_tOhi[(size_t)DIM*DIM];
__device__ __half g_Qhi[(size_t)MQ * DIM];
__device__ __half g_Khi[(size_t)MK * DIM];
__device__ __half g_Vhi[(size_t)MK * DIM];
__device__ __half g_Chi[(size_t)MQ * DIM];
__device__ float  g_S[(size_t)NB*NH*LQ*LKK];
__device__ __half g_P[(size_t)NB*NH*LQ*LKK];

// ------------------------- helpers -------------------------
__device__ __forceinline__ uint32_t smem_to_u32(const void* p) {
    uint32_t a;
    asm("{ .reg .u64 t; cvta.to.shared.u64 t, %1; cvt.u32.u64 %0, t; }" : "=r"(a) : "l"(p));
    return a;
}
__device__ __forceinline__ void ldsm_x4(uint32_t* r, uint32_t addr) {
    asm volatile("ldmatrix.sync.aligned.m8n8.x4.shared.b16 {%0,%1,%2,%3}, [%4];"
        : "=r"(r[0]), "=r"(r[1]), "=r"(r[2]), "=r"(r[3]) : "r"(addr));
}
__device__ __forceinline__ void ldsm_x4_t(uint32_t* r, uint32_t addr) {
    asm volatile("ldmatrix.sync.aligned.m8n8.x4.trans.shared.b16 {%0,%1,%2,%3}, [%4];"
        : "=r"(r[0]), "=r"(r[1]), "=r"(r[2]), "=r"(r[3]) : "r"(addr));
}
__device__ __forceinline__ void mma16816(float* d, const uint32_t* a, const uint32_t* b) {
    asm volatile("mma.sync.aligned.m16n8k16.row.col.f32.f16.f16.f32 "
        "{%0,%1,%2,%3}, {%4,%5,%6,%7}, {%8,%9}, {%0,%1,%2,%3};"
        : "+f"(d[0]), "+f"(d[1]), "+f"(d[2]), "+f"(d[3])
        : "r"(a[0]), "r"(a[1]), "r"(a[2]), "r"(a[3]), "r"(b[0]), "r"(b[1]));
}
__device__ __forceinline__ uint32_t h2bits(float a, float b) {
    __half2 h = __floats2half2_rn(a, b);
    return *(uint32_t*)&h;
}
__device__ __forceinline__ void cp16(uint32_t saddr, const void* g) {
    asm volatile("cp.async.cg.shared.global [%0], [%1], 16;" :: "r"(saddr), "l"(g));
}
#define CP_COMMIT() asm volatile("cp.async.commit_group;" ::: "memory")
#define CP_WAIT0()  asm volatile("cp.async.wait_group 0;" ::: "memory")
#define CP_WAIT1()  asm volatile("cp.async.wait_group 1;" ::: "memory")

// ------------------------- fused conversion -------------------------
#define N4_A (MQ * DIM / 4)
#define N4_V (MK * DIM / 4)
#define N4_W (3 * DIM * DIM / 4)
#define N4_O (DIM * DIM / 4)
#define N4_TOTAL (N4_A + N4_V + N4_W + N4_O)

__global__ __launch_bounds__(256) void cvt_all(
    const float4* __restrict__ text, const float4* __restrict__ vision,
    const float4* __restrict__ ipw,  const float4* __restrict__ outw,
    uint2* __restrict__ tA, uint2* __restrict__ tV,
    uint2* __restrict__ tW, uint2* __restrict__ tO)
{
    int i = blockIdx.x * blockDim.x + threadIdx.x;
    if (i >= N4_TOTAL) return;
    const float4* src; uint2* dst; float sc; int j;
    if (i < N4_A)                   { src = text;   dst = tA; sc = 1.0f; j = i; }
    else if (i < N4_A + N4_V)       { src = vision; dst = tV; sc = 1.0f; j = i - N4_A; }
    else if (i < N4_A + N4_V + N4_W){ src = ipw;    dst = tW; sc = WUP;  j = i - N4_A - N4_V; }
    else                            { src = outw;   dst = tO; sc = WUP;  j = i - N4_A - N4_V - N4_W; }
    float4 v = src[j];
    dst[j] = make_uint2(h2bits(v.x * sc, v.y * sc), h2bits(v.z * sc, v.w * sc));
}

// ------------------------- mma.sync fp16 GEMM 128x128 (Q / out-proj) -------------------------
#define GT_TILE 8192
#define GSM_TOTAL (4 * GT_TILE)

template<int MODE>
__global__ __launch_bounds__(256, 2) void gemm_mma(
    const __half* __restrict__ Ahi, const __half* __restrict__ Whi,
    const float* __restrict__ bias, const float* __restrict__ res,
    float* __restrict__ C,
    __half* __restrict__ h0,
    int M, int N, int K)
{
    extern __shared__ char sm[];
    const uint32_t sb = smem_to_u32(sm);

    const int tid  = threadIdx.x;
    const int wid  = tid >> 5;
    const int lane = tid & 31;
    const int bm = blockIdx.y * 128;
    const int bn = blockIdx.x * 128;
    const int m0 = (wid >> 2) * 64;
    const int n0 = (wid & 3) * 32;

    int lrow[2], lsl[2], loff[2];
#pragma unroll
    for (int i = 0; i < 2; i++) {
        int u = tid + i * 256;
        lrow[i] = u >> 2;
        lsl[i]  = u & 3;
        loff[i] = lrow[i] * 64 + ((lsl[i] << 4) ^ (((lrow[i] >> 1) & 3) << 4));
    }

    const int arow_l = lane & 15;
    const int a_hi   = lane >> 4;
    const int brow_l = (lane & 7) + ((lane & 16) ? 8 : 0);
    const int b_hi   = (lane & 8) ? 1 : 0;
    const int gid = lane >> 2, tig = lane & 3;

    float acc[4][4][4];
#pragma unroll
    for (int i = 0; i < 4; i++)
#pragma unroll
        for (int j = 0; j < 4; j++)
#pragma unroll
            for (int l = 0; l < 4; l++) acc[i][j][l] = 0.f;

    const int nch = K >> 5;

    {
#pragma unroll
        for (int i = 0; i < 2; i++) {
            const int col = lsl[i] * 8;
            cp16(sb + loff[i],           Ahi + (size_t)(bm + lrow[i]) * K + col);
            cp16(sb + GT_TILE + loff[i], Whi + (size_t)(bn + lrow[i]) * K + col);
        }
        CP_COMMIT();
    }

    for (int c = 0; c < nch; c++) {
        CP_WAIT0();
        __syncthreads();
        if (c + 1 < nch) {
            const uint32_t base = sb + ((c + 1) & 1) * 2 * GT_TILE;
            const int coff = (c + 1) * 32;
#pragma unroll
            for (int i = 0; i < 2; i++) {
                const int col = coff + lsl[i] * 8;
                cp16(base + loff[i],           Ahi + (size_t)(bm + lrow[i]) * K + col);
                cp16(base + GT_TILE + loff[i], Whi + (size_t)(bn + lrow[i]) * K + col);
            }
            CP_COMMIT();
        }
        const uint32_t tb = sb + (c & 1) * 2 * GT_TILE;
#pragma unroll
        for (int ks = 0; ks < 2; ks++) {
            uint32_t ah[4][4];
#pragma unroll
            for (int mf = 0; mf < 4; mf++) {
                const int row = m0 + mf * 16 + arow_l;
                const int sl  = ks * 2 + a_hi;
                ldsm_x4(ah[mf], tb + row * 64 + ((sl << 4) ^ (((row >> 1) & 3) << 4)));
            }
            uint32_t bh[2][4];
#pragma unroll
            for (int np = 0; np < 2; np++) {
                const int row = n0 + np * 16 + brow_l;
                const int sl  = ks * 2 + b_hi;
                ldsm_x4(bh[np], tb + GT_TILE + row * 64 + ((sl << 4) ^ (((row >> 1) & 3) << 4)));
            }
#pragma unroll
            for (int mf = 0; mf < 4; mf++)
#pragma unroll
                for (int np = 0; np < 2; np++)
#pragma unroll
                    for (int half = 0; half < 2; half++)
                        mma16816(acc[mf][np * 2 + half], ah[mf], &bh[np][half * 2]);
        }
    }

#pragma unroll
    for (int mf = 0; mf < 4; mf++) {
        const int mrow0 = bm + m0 + mf * 16 + gid;
#pragma unroll
        for (int nf = 0; nf < 4; nf++) {
            const int col = bn + n0 + nf * 8 + tig * 2;
            const float2 bia = *(const float2*)&bias[col];
            float* d = acc[mf][nf];
            float v00 = d[0] * WINV + bia.x, v01 = d[1] * WINV + bia.y;
            float v10 = d[2] * WINV + bia.x, v11 = d[3] * WINV + bia.y;
            if (MODE == 0) {
                const size_t i0 = (size_t)mrow0 * N + col;
                const size_t i1 = (size_t)(mrow0 + 8) * N + col;
                if (res) {
                    float2 r0 = *(const float2*)&res[i0];
                    float2 r1 = *(const float2*)&res[i1];
                    v00 += r0.x; v01 += r0.y; v10 += r1.x; v11 += r1.y;
                }
                *(float2*)&C[i0] = make_float2(v00, v01);
                *(float2*)&C[i1] = make_float2(v10, v11);
            } else {
                v00 *= QSCALE; v01 *= QSCALE; v10 *= QSCALE; v11 *= QSCALE;
                const size_t i0 = (size_t)mrow0 * DIM + col;
                const size_t i1 = (size_t)(mrow0 + 8) * DIM + col;
                *(uint32_t*)&h0[i0] = h2bits(v00, v01);
                *(uint32_t*)&h0[i1] = h2bits(v10, v11);
            }
        }
    }
}

// ------------------------- KV GEMM: 128x256 tile, 3-stage (R9-verified) -------------------------
#define GA_TILE 8192
#define GW_TILE 16384
#define GSTAGE  (GA_TILE + GW_TILE)
#define GW_TOTAL (3 * GSTAGE)

__global__ __launch_bounds__(256, 1) void gemm_kv(
    const __half* __restrict__ Ahi, const __half* __restrict__ Whi,
    const float* __restrict__ bias,
    __half* __restrict__ h0, __half* __restrict__ h1,
    int M, int N, int K)
{
    extern __shared__ char sm[];
    const uint32_t sb = smem_to_u32(sm);

    const int tid  = threadIdx.x;
    const int wid  = tid >> 5;
    const int lane = tid & 31;
    const int bm = blockIdx.y * 128;
    const int bn = blockIdx.x * 256;
    const int m0 = (wid >> 2) * 64;
    const int n0 = (wid & 3) * 64;

    int arow_g[2], asl[2], aoff[2];
#pragma unroll
    for (int i = 0; i < 2; i++) {
        int u = tid + i * 256;
        arow_g[i] = u >> 2;
        asl[i]    = u & 3;
        aoff[i]   = arow_g[i] * 64 + ((asl[i] << 4) ^ (((arow_g[i] >> 1) & 3) << 4));
    }
    int wrow_g[4], wsl[4], woff[4];
#pragma unroll
    for (int i = 0; i < 4; i++) {
        int u = tid + i * 256;
        wrow_g[i] = u >> 2;
        wsl[i]    = u & 3;
        woff[i]   = wrow_g[i] * 64 + ((wsl[i] << 4) ^ (((wrow_g[i] >> 1) & 3) << 4));
    }

    const int arow_l = lane & 15;
    const int a_hi   = lane >> 4;
    const int brow_l = (lane & 7) + ((lane & 16) ? 8 : 0);
    const int b_hi   = (lane & 8) ? 1 : 0;
    const int gid = lane >> 2, tig = lane & 3;

    float acc[4][8][4];
#pragma unroll
    for (int i = 0; i < 4; i++)
#pragma unroll
        for (int j = 0; j < 8; j++)
#pragma unroll
            for (int l = 0; l < 4; l++) acc[i][j][l] = 0.f;

    const int nch = K >> 5;

#pragma unroll
    for (int c0 = 0; c0 < 2; c0++) {
        const uint32_t base = sb + c0 * GSTAGE;
        const int coff = c0 * 32;
#pragma unroll
        for (int i = 0; i < 2; i++)
            cp16(base + aoff[i], Ahi + (size_t)(bm + arow_g[i]) * K + coff + asl[i] * 8);
#pragma unroll
        for (int i = 0; i < 4; i++)
            cp16(base + GA_TILE + woff[i], Whi + (size_t)(bn + wrow_g[i]) * K + coff + wsl[i] * 8);
        CP_COMMIT();
    }

    int stg = 0;
    for (int c = 0; c < nch; c++) {
        if (c + 1 < nch) { CP_WAIT1(); } else { CP_WAIT0(); }
        __syncthreads();
        if (c + 2 < nch) {
            int ns = stg + 2; if (ns >= 3) ns -= 3;
            const uint32_t base = sb + ns * GSTAGE;
            const int coff = (c + 2) * 32;
#pragma unroll
            for (int i = 0; i < 2; i++)
                cp16(base + aoff[i], Ahi + (size_t)(bm + arow_g[i]) * K + coff + asl[i] * 8);
#pragma unroll
            for (int i = 0; i < 4; i++)
                cp16(base + GA_TILE + woff[i], Whi + (size_t)(bn + wrow_g[i]) * K + coff + wsl[i] * 8);
            CP_COMMIT();
        }
        const uint32_t tb = sb + stg * GSTAGE;
#pragma unroll
        for (int ks = 0; ks < 2; ks++) {
            uint32_t ah[4][4];
#pragma unroll
            for (int mf = 0; mf < 4; mf++) {
                const int row = m0 + mf * 16 + arow_l;
                const int sl  = ks * 2 + a_hi;
                ldsm_x4(ah[mf], tb + row * 64 + ((sl << 4) ^ (((row >> 1) & 3) << 4)));
            }
            uint32_t bh[4][4];
#pragma unroll
            for (int nf4 = 0; nf4 < 4; nf4++) {
                const int row = n0 + nf4 * 16 + brow_l;
                const int sl  = ks * 2 + b_hi;
                ldsm_x4(bh[nf4], tb + GA_TILE + row * 64 + ((sl << 4) ^ (((row >> 1) & 3) << 4)));
            }
#pragma unroll
            for (int mf = 0; mf < 4; mf++)
#pragma unroll
                for (int nf4 = 0; nf4 < 4; nf4++)
#pragma unroll
                    for (int half = 0; half < 2; half++)
                        mma16816(acc[mf][nf4 * 2 + half], ah[mf], &bh[nf4][half * 2]);
        }
        stg++; if (stg == 3) stg = 0;
    }

#pragma unroll
    for (int mf = 0; mf < 4; mf++) {
        const int mrow0 = bm + m0 + mf * 16 + gid;
#pragma unroll
        for (int nf = 0; nf < 8; nf++) {
            const int col = bn + n0 + nf * 8 + tig * 2;
            const float2 bia = *(const float2*)&bias[col];
            float* d = acc[mf][nf];
            float v00 = d[0] * WINV + bia.x, v01 = d[1] * WINV + bia.y;
            float v10 = d[2] * WINV + bia.x, v11 = d[3] * WINV + bia.y;
            __half* H = h0;
            int cc = col;
            if (col >= DIM) { H = h1; cc = col - DIM; }
            const size_t i0 = (size_t)mrow0 * DIM + cc;
            const size_t i1 = (size_t)(mrow0 + 8) * DIM + cc;
            *(uint32_t*)&H[i0] = h2bits(v00, v01);
            *(uint32_t*)&H[i1] = h2bits(v10, v11);
        }
    }
}

// ------------------------- scores: S[bh][q][k] = Q @ K^T -------------------------
__global__ __launch_bounds__(256, 3) void scores_mma()
{
    __shared__ char sm[32768];
    const uint32_t sb = smem_to_u32(sm);
    const uint32_t sW = sb + 16384;

    const int tid  = threadIdx.x;
    const int wid  = tid >> 5;
    const int lane = tid & 31;
    const int bh = blockIdx.z;
    const int b  = bh >> 4;
    const int h  = bh & 15;
    const int bm = blockIdx.y * 128;
    const int bn = blockIdx.x * 128;
    const int m0 = (wid >> 2) * 64;
    const int n0 = (wid & 3) * 32;

#pragma unroll
    for (int i = 0; i < 4; i++) {
        int u = tid + i * 256;
        int row = u >> 3, sl = u & 7;
        int off = row * 128 + ((sl << 4) ^ ((row & 7) << 4));
        cp16(sb + off, g_Qhi + (size_t)(b * LQ  + bm + row) * DIM + h * HD + sl * 8);
        cp16(sW + off, g_Khi + (size_t)(b * LKK + bn + row) * DIM + h * HD + sl * 8);
    }
    CP_COMMIT();

    const int arow_l = lane & 15;
    const int axor   = (arow_l & 7) << 4;
    const int akb    = (lane >> 4) * 16;
    const int brow_l = (lane & 7) + ((lane & 16) ? 8 : 0);
    const int bxor   = (lane & 7) << 4;
    const int bkb    = (lane & 8) ? 16 : 0;
    const int gid = lane >> 2, tig = lane & 3;

    float acc[4][4][4];
#pragma unroll
    for (int i = 0; i < 4; i++)
#pragma unroll
        for (int j = 0; j < 4; j++)
#pragma unroll
            for (int l = 0; l < 4; l++) acc[i][j][l] = 0.f;

    CP_WAIT0();
    __syncthreads();

#pragma unroll
    for (int ks = 0; ks < 4; ks++) {
        const int akoff = (ks * 32 + akb) ^ axor;
        const int bkoff = (ks * 32 + bkb) ^ bxor;
        uint32_t ah[4][4];
#pragma unroll
        for (int mf = 0; mf < 4; mf++)
            ldsm_x4(ah[mf], sb + (m0 + mf * 16 + arow_l) * 128 + akoff);
        uint32_t bhh[2][4];
#pragma unroll
        for (int np = 0; np < 2; np++)
            ldsm_x4(bhh[np], sW + (n0 + np * 16 + brow_l) * 128 + bkoff);
#pragma unroll
        for (int mf = 0; mf < 4; mf++)
#pragma unroll
            for (int np = 0; np < 2; np++)
#pragma unroll
                for (int half = 0; half < 2; half++)
                    mma16816(acc[mf][np * 2 + half], ah[mf], &bhh[np][half * 2]);
    }

    float* Sout = g_S + (size_t)bh * LQ * LKK;
#pragma unroll
    for (int mf = 0; mf < 4; mf++) {
        const int mrow0 = bm + m0 + mf * 16 + gid;
#pragma unroll
        for (int nf = 0; nf < 4; nf++) {
            const int col = bn + n0 + nf * 8 + tig * 2;
            float* d = acc[mf][nf];
            *(float2*)&Sout[(size_t)mrow0 * LKK + col]       = make_float2(d[0], d[1]);
            *(float2*)&Sout[(size_t)(mrow0 + 8) * LKK + col] = make_float2(d[2], d[3]);
        }
    }
}

// ------------------------- softmax + attnw + P fp16 (warp-per-row) -------------------------
__global__ __launch_bounds__(256) void softmax_aw(float* __restrict__ attnw)
{
    __shared__ float saw[8 * 1028];
    const int rq  = blockIdx.x;
    const int b   = rq >> 9;
    const int q   = rq & 511;
    const int tid = threadIdx.x;
    const int w   = tid >> 5, lane = tid & 31;

    float aw[32];
#pragma unroll
    for (int j = 0; j < 32; j++) aw[j] = 0.f;

#pragma unroll
    for (int hh = 0; hh < 2; hh++) {
        const int h = w + hh * 8;
        const size_t base = ((size_t)(b * NH + h) * LQ + q) * LKK;
        float v[32];
#pragma unroll
        for (int j = 0; j < 8; j++)
            *(float4*)&v[j * 4] = *(const float4*)(g_S + base + j * 128 + lane * 4);
        float s = 0.f;
#pragma unroll
        for (int j = 0; j < 32; j++) { v[j] = __expf(v[j]); s += v[j]; }
#pragma unroll
        for (int o = 16; o > 0; o >>= 1) s += __shfl_xor_sync(0xffffffffu, s, o);
        const float inv = 1.0f / s;
#pragma unroll
        for (int j = 0; j < 32; j++) { v[j] *= inv; aw[j] += v[j]; }
#pragma unroll
        for (int j = 0; j < 8; j++) {
            uint2 p = make_uint2(h2bits(v[j*4], v[j*4+1]), h2bits(v[j*4+2], v[j*4+3]));
            *(uint2*)(g_P + base + j * 128 + lane * 4) = p;
        }
    }

#pragma unroll
    for (int j = 0; j < 8; j++)
        *(float4*)&saw[w * 1028 + j * 128 + lane * 4] = *(float4*)&aw[j * 4];
    __syncthreads();
    float4 acc = make_float4(0.f, 0.f, 0.f, 0.f);
#pragma unroll
    for (int ww = 0; ww < 8; ww++) {
        float4 p = *(float4*)&saw[ww * 1028 + tid * 4];
        acc.x += p.x; acc.y += p.y; acc.z += p.z; acc.w += p.w;
    }
    const float invh = 1.0f / NH;
    acc.x *= invh; acc.y *= invh; acc.z *= invh; acc.w *= invh;
    *(float4*)&attnw[(size_t)rq * LKK + tid * 4] = acc;
}

// ------------------------- ctx: P @ V -------------------------
#define CTX_STAGE 24576
__global__ __launch_bounds__(256, 2) void ctx_mma()
{
    __shared__ char sm[2 * CTX_STAGE];
    const uint32_t sb = smem_to_u32(sm);

    const int tid  = threadIdx.x;
    const int wid  = tid >> 5;
    const int lane = tid & 31;
    const int bh = blockIdx.y;
    const int b  = bh >> 4;
    const int h  = bh & 15;
    const int bm = blockIdx.x * 128;
    const int m0  = (wid >> 2) * 64;
    const int nv0 = (wid & 3) * 16;

    int prow[4], psl[4], poff_s[4];
#pragma unroll
    for (int i = 0; i < 4; i++) {
        int u = tid + i * 256;
        prow[i] = u >> 3; psl[i] = u & 7;
        poff_s[i] = prow[i] * 128 + ((psl[i] << 4) ^ ((prow[i] & 7) << 4));
    }
    int vrow[2], vsl[2], voff_s[2];
#pragma unroll
    for (int i = 0; i < 2; i++) {
        int u = tid + i * 256;
        vrow[i] = u >> 3; vsl[i] = u & 7;
        voff_s[i] = vrow[i] * 128 + ((vsl[i] << 4) ^ ((vrow[i] & 7) << 4));
    }

    const int arow_l = lane & 15;
    const int axor   = (arow_l & 7) << 4;
    const int akb    = (lane >> 4) * 16;
    const int vkey_l = ((lane >> 3) & 1) * 8 + (lane & 7);
    const int vdim   = nv0 + ((lane >> 4) ? 8 : 0);
    const int gid = lane >> 2, tig = lane & 3;

    const __half* Pbase = g_P + (size_t)bh * LQ * LKK;

    float acc[4][2][4];
#pragma unroll
    for (int i = 0; i < 4; i++)
#pragma unroll
        for (int j = 0; j < 2; j++)
#pragma unroll
            for (int l = 0; l < 4; l++) acc[i][j][l] = 0.f;

    {
#pragma unroll
        for (int i = 0; i < 4; i++)
            cp16(sb + poff_s[i], Pbase + (size_t)(bm + prow[i]) * LKK + psl[i] * 8);
#pragma unroll
        for (int i = 0; i < 2; i++)
            cp16(sb + 16384 + voff_s[i],
                 g_Vhi + (size_t)(b * LKK + vrow[i]) * DIM + h * HD + vsl[i] * 8);
        CP_COMMIT();
    }

    for (int kc = 0; kc < 16; kc++) {
        CP_WAIT0();
        __syncthreads();
        if (kc + 1 < 16) {
            const uint32_t base = sb + ((kc + 1) & 1) * CTX_STAGE;
            const int koff = (kc + 1) * 64;
#pragma unroll
            for (int i = 0; i < 4; i++)
                cp16(base + poff_s[i], Pbase + (size_t)(bm + prow[i]) * LKK + koff + psl[i] * 8);
#pragma unroll
            for (int i = 0; i < 2; i++)
                cp16(base + 16384 + voff_s[i],
                     g_Vhi + (size_t)(b * LKK + koff + vrow[i]) * DIM + h * HD + vsl[i] * 8);
            CP_COMMIT();
        }
        const uint32_t pb = sb + (kc & 1) * CTX_STAGE;
        const uint32_t vb = pb + 16384;
#pragma unroll
        for (int ks = 0; ks < 4; ks++) {
            const int akoff = (ks * 32 + akb) ^ axor;
            uint32_t pah[4][4];
#pragma unroll
            for (int mf = 0; mf < 4; mf++)
                ldsm_x4(pah[mf], pb + (m0 + mf * 16 + arow_l) * 128 + akoff);
            const int key = ks * 16 + vkey_l;
            uint32_t vh[4];
            ldsm_x4_t(vh, vb + key * 128 + ((vdim * 2) ^ ((key & 7) << 4)));
#pragma unroll
            for (int mf = 0; mf < 4; mf++)
#pragma unroll
                for (int g = 0; g < 2; g++)
                    mma16816(acc[mf][g], pah[mf], &vh[g * 2]);
        }
    }

#pragma unroll
    for (int mf = 0; mf < 4; mf++) {
        const int mrow0 = b * LQ + bm + m0 + mf * 16 + gid;
#pragma unroll
        for (int g = 0; g < 2; g++) {
            const int col = h * HD + nv0 + g * 8 + tig * 2;
            float* d = acc[mf][g];
            *(uint32_t*)&g_Chi[(size_t)mrow0 * DIM + col]       = h2bits(d[0], d[1]);
            *(uint32_t*)&g_Chi[(size_t)(mrow0 + 8) * DIM + col] = h2bits(d[2], d[3]);
        }
    }
}

// ------------------------- layernorm -------------------------
__global__ __launch_bounds__(256) void ln_kernel(
    const float* __restrict__ X, const float* __restrict__ gam,
    const float* __restrict__ bet, float* __restrict__ out)
{
    __shared__ float red[64];
    __shared__ float s_mu, s_rinv;
    const int r = blockIdx.x, tid = threadIdx.x;
    const float* x = X + (size_t)r * DIM;
    float4 v = *(const float4*)&x[tid * 4];
    float s  = v.x + v.y + v.z + v.w;
    float sq = v.x * v.x + v.y * v.y + v.z * v.z + v.w * v.w;
#pragma unroll
    for (int o = 16; o > 0; o >>= 1) {
        s  += __shfl_xor_sync(0xffffffffu, s, o);
        sq += __shfl_xor_sync(0xffffffffu, sq, o);
    }
    const int w = tid >> 5;
    if ((tid & 31) == 0) { red[w] = s; red[32 + w] = sq; }
    __syncthreads();
    if (tid == 0) {
        float S = 0, Q = 0;
        for (int i = 0; i < 8; i++) { S += red[i]; Q += red[32 + i]; }
        float mu = S * (1.0f / DIM);
        float var = Q * (1.0f / DIM) - mu * mu;
        s_mu = mu;
        s_rinv = rsqrtf(var + EPSV);
    }
    __syncthreads();
    const float mu = s_mu, rinv = s_rinv;
    float4 gg = *(const float4*)&gam[tid * 4];
    float4 bb = *(const float4*)&bet[tid * 4];
    float4 o;
    o.x = (v.x - mu) * rinv * gg.x + bb.x;
    o.y = (v.y - mu) * rinv * gg.y + bb.y;
    o.z = (v.z - mu) * rinv * gg.z + bb.z;
    o.w = (v.w - mu) * rinv * gg.w + bb.w;
    *(float4*)&out[(size_t)r * DIM + tid * 4] = o;
}

// ------------------------- launch -------------------------
extern "C" void kernel_launch(void* const* d_in, const int* in_sizes, int n_in,
                              void* d_out, int out_size)
{
    const float* text   = (const float*)d_in[0];
    const float* vision = (const float*)d_in[1];
    const float* ipw    = (const float*)d_in[2];
    const float* ipb    = (const float*)d_in[3];
    const float* outw   = (const float*)d_in[4];
    const float* outb   = (const float*)d_in[5];
    const float* lng    = (const float*)d_in[6];
    const float* lnb    = (const float*)d_in[7];

    float* out   = (float*)d_out;
    float* attnw = out + (size_t)MQ * DIM;

    float* attp;
    cudaGetSymbolAddress((void**)&attp, g_att);

    __half *tAhi, *tVhi, *tWhi, *tOhi, *Qhi, *Khi, *Vhi, *Chi;
    cudaGetSymbolAddress((void**)&tAhi, g_tAhi);
    cudaGetSymbolAddress((void**)&tVhi, g_tVhi);
    cudaGetSymbolAddress((void**)&tWhi, g_tWhi);
    cudaGetSymbolAddress((void**)&tOhi, g_tOhi);
    cudaGetSymbolAddress((void**)&Qhi, g_Qhi);
    cudaGetSymbolAddress((void**)&Khi, g_Khi);
    cudaGetSymbolAddress((void**)&Vhi, g_Vhi);
    cudaGetSymbolAddress((void**)&Chi, g_Chi);

    cudaFuncSetAttribute(gemm_mma<0>, cudaFuncAttributeMaxDynamicSharedMemorySize, GSM_TOTAL);
    cudaFuncSetAttribute(gemm_mma<1>, cudaFuncAttributeMaxDynamicSharedMemorySize, GSM_TOTAL);
    cudaFuncSetAttribute(gemm_kv, cudaFuncAttributeMaxDynamicSharedMemorySize, GW_TOTAL);

    cvt_all<<<(N4_TOTAL + 255) / 256, 256>>>(
        (const float4*)text, (const float4*)vision, (const float4*)ipw, (const float4*)outw,
        (uint2*)tAhi, (uint2*)tVhi, (uint2*)tWhi, (uint2*)tOhi);

    // Q (scaled fp16) = 0.125*(text @ Wq^T + bq)   [128x128 tiles]
    gemm_mma<1><<<dim3(DIM / 128, MQ / 128), 256, GSM_TOTAL>>>(
        tAhi, tWhi, ipb, nullptr, nullptr, Qhi, MQ, DIM, DIM);
    // [K|V] fp16 = vision @ [Wk|Wv]^T + [bk|bv]    [128x256 tiles, 512 CTAs]
    gemm_kv<<<dim3(2 * DIM / 256, MK / 128), 256, GW_TOTAL>>>(
        tVhi, tWhi + (size_t)DIM * DIM, ipb + DIM, Khi, Vhi, MK, 2 * DIM, DIM);

    scores_mma<<<dim3(LKK / 128, LQ / 128, NB * NH), 256>>>();
    softmax_aw<<<MQ, 256>>>(attnw);
    ctx_mma<<<dim3(LQ / 128, NB * NH), 256>>>();

    // attended = ctx @ out_w^T + out_b + text      [128x128 tiles]
    gemm_mma<0><<<dim3(DIM / 128, MQ / 128), 256, GSM_TOTAL>>>(
        Chi, tOhi, outb, text, attp, nullptr, MQ, DIM, DIM);
    ln_kernel<<<MQ, 256>>>(attp, lng, lnb, out);
}